// round 13
// baseline (speedup 1.0000x reference)
#include <cuda_runtime.h>
#include <cuda_bf16.h>
#include <math.h>

// ---------------------------------------------------------------------------
// Problem constants
// ---------------------------------------------------------------------------
#define BB   2
#define NN   4096
#define DD   384
#define HH   6
#define DH   64
#define ROWS (BB * NN)          // 8192
#define KNN_K 8
#define RSQ  (3 * DD)           // 1152, QKV row stride

// packed bf16 weight buffer offsets
#define OFF_QKV 0
#define OFF_GQ  442368
#define OFF_ATT 884736
#define OFF_MRG 1032192
#define OFF_FF1 1327104
#define OFF_FF2 1622016
#define TOTW    1916928

// Q pre-scale: (1/8) * log2(e)  -> softmax via ex2.approx
#define QSCALE 0.18033688011112042f

// ---------------------------------------------------------------------------
// Scratch (global device arrays; no allocations anywhere)
// ---------------------------------------------------------------------------
__device__ __nv_bfloat16 g_NF   [ROWS * DD];
__device__ __nv_bfloat16 g_QKV  [ROWS * RSQ];      // [row][q|k|v x 384]
__device__ float         g_GQ   [ROWS * DD];
__device__ float         g_GK   [ROWS * DD];
__device__ float         g_GV   [ROWS * DD];
__device__ __nv_bfloat16 g_ATTN [ROWS * DD];
__device__ __nv_bfloat16 g_GEOM [ROWS * DD];
__device__ float         g_F2   [ROWS * DD];
__device__ __nv_bfloat16 g_H2   [ROWS * DD];
__device__ __nv_bfloat16 g_G1   [ROWS * 2 * DD];
__device__ __nv_bfloat16 g_WB   [TOTW];
__device__ __nv_bfloat16 g_WM2  [2 * DD * DD];     // fused attn-out x merge
__device__ float         g_BC   [DD];              // combined merge bias
__device__ float         g_ZB   [DD];              // zeros (static init)
__device__ int           g_KNN  [BB * NN * KNN_K];

// ---------------------------------------------------------------------------
// asm helpers
// ---------------------------------------------------------------------------
__device__ __forceinline__ unsigned sptr(const void* p) {
    return (unsigned)__cvta_generic_to_shared(p);
}
__device__ __forceinline__ void cpa16(unsigned dst, const void* src) {
    asm volatile("cp.async.cg.shared.global [%0], [%1], 16;" :: "r"(dst), "l"(src));
}
__device__ __forceinline__ void cp_commit() {
    asm volatile("cp.async.commit_group;" ::: "memory");
}
template <int N>
__device__ __forceinline__ void cp_wait() {
    asm volatile("cp.async.wait_group %0;" :: "n"(N) : "memory");
}
__device__ __forceinline__ void ldsm_x4(unsigned& r0, unsigned& r1,
                                        unsigned& r2, unsigned& r3, unsigned a) {
    asm volatile("ldmatrix.sync.aligned.m8n8.x4.shared.b16 {%0,%1,%2,%3}, [%4];"
        : "=r"(r0), "=r"(r1), "=r"(r2), "=r"(r3) : "r"(a));
}
__device__ __forceinline__ void ldsm_x4_t(unsigned& r0, unsigned& r1,
                                          unsigned& r2, unsigned& r3, unsigned a) {
    asm volatile("ldmatrix.sync.aligned.m8n8.x4.trans.shared.b16 {%0,%1,%2,%3}, [%4];"
        : "=r"(r0), "=r"(r1), "=r"(r2), "=r"(r3) : "r"(a));
}
__device__ __forceinline__ void mma_bf16(float* c,
    unsigned a0, unsigned a1, unsigned a2, unsigned a3, unsigned b0, unsigned b1)
{
    asm volatile(
        "mma.sync.aligned.m16n8k16.row.col.f32.bf16.bf16.f32 "
        "{%0,%1,%2,%3}, {%4,%5,%6,%7}, {%8,%9}, {%0,%1,%2,%3};"
        : "+f"(c[0]), "+f"(c[1]), "+f"(c[2]), "+f"(c[3])
        : "r"(a0), "r"(a1), "r"(a2), "r"(a3), "r"(b0), "r"(b1));
}
__device__ __forceinline__ unsigned pack_bf16(float lo, float hi) {
    unsigned r;
    asm("cvt.rn.bf16x2.f32 %0, %1, %2;" : "=r"(r) : "f"(hi), "f"(lo));
    return r;
}
__device__ __forceinline__ float ex2f(float x) {
    float r;
    asm("ex2.approx.f32 %0, %1;" : "=f"(r) : "f"(x));
    return r;
}

// ---------------------------------------------------------------------------
// Weight conversion: 8 fp32 matrices -> one packed bf16 buffer
// ---------------------------------------------------------------------------
__global__ void __launch_bounds__(256) wcvt_kernel(
    const float* __restrict__ a0, const float* __restrict__ a1,
    const float* __restrict__ a2, const float* __restrict__ a3,
    const float* __restrict__ a4, const float* __restrict__ a5,
    const float* __restrict__ a6, const float* __restrict__ a7,
    __nv_bfloat16* __restrict__ o)
{
    int i4 = (blockIdx.x * 256 + threadIdx.x) * 4;
    if (i4 >= TOTW) return;
    const float* src; int loc;
    if      (i4 < OFF_GQ)           { src = a0; loc = i4; }
    else if (i4 < OFF_GQ + 147456)  { src = a1; loc = i4 - OFF_GQ; }
    else if (i4 < OFF_GQ + 294912)  { src = a2; loc = i4 - OFF_GQ - 147456; }
    else if (i4 < OFF_ATT)          { src = a3; loc = i4 - OFF_GQ - 294912; }
    else if (i4 < OFF_MRG)          { src = a4; loc = i4 - OFF_ATT; }
    else if (i4 < OFF_FF1)          { src = a5; loc = i4 - OFF_MRG; }
    else if (i4 < OFF_FF2)          { src = a6; loc = i4 - OFF_FF1; }
    else                            { src = a7; loc = i4 - OFF_FF2; }
    float4 v = *(const float4*)(src + loc);
    uint2 u;
    u.x = pack_bf16(v.x, v.y);
    u.y = pack_bf16(v.z, v.w);
    *(uint2*)(o + i4) = u;
}

// copy bottom half of merge weight (bf16) into WM2 bottom
__global__ void __launch_bounds__(256) wcopy_kernel(
    const __nv_bfloat16* __restrict__ src, __nv_bfloat16* __restrict__ dst)
{
    int i8 = (blockIdx.x * 256 + threadIdx.x) * 8;
    if (i8 < DD * DD)
        *(uint4*)(dst + i8) = *(const uint4*)(src + i8);
}

// combined merge bias: bc[j] = sum_i b_ao[i] * wm[i*DD+j] + b_merge[j]
__global__ void __launch_bounds__(DD) biascomb_kernel(
    const float* __restrict__ b_ao, const float* __restrict__ wm,
    const float* __restrict__ b_merge, float* __restrict__ bc)
{
    int j = threadIdx.x;
    float s = b_merge[j];
    for (int i = 0; i < DD; i++) s = fmaf(b_ao[i], wm[i * DD + j], s);
    bc[j] = s;
}

// ---------------------------------------------------------------------------
// LayerNorm: one block per row, 128 threads, bf16 output
// ---------------------------------------------------------------------------
__global__ void __launch_bounds__(128) ln_kernel(
    const float* __restrict__ x, const float* __restrict__ g,
    const float* __restrict__ be, __nv_bfloat16* __restrict__ out)
{
    const int row = blockIdx.x;
    const int tid = threadIdx.x;
    const float* xr = x + (size_t)row * DD;

    float v0 = xr[tid], v1 = xr[tid + 128], v2 = xr[tid + 256];

    __shared__ float red[4];
    float s = v0 + v1 + v2;
    #pragma unroll
    for (int off = 16; off; off >>= 1) s += __shfl_xor_sync(0xffffffffu, s, off);
    if ((tid & 31) == 0) red[tid >> 5] = s;
    __syncthreads();
    float mean = (red[0] + red[1] + red[2] + red[3]) * (1.0f / 384.0f);

    float d0 = v0 - mean, d1 = v1 - mean, d2 = v2 - mean;
    float sq = d0 * d0 + d1 * d1 + d2 * d2;
    #pragma unroll
    for (int off = 16; off; off >>= 1) sq += __shfl_xor_sync(0xffffffffu, sq, off);
    __syncthreads();
    if ((tid & 31) == 0) red[tid >> 5] = sq;
    __syncthreads();
    float var = (red[0] + red[1] + red[2] + red[3]) * (1.0f / 384.0f);
    float inv = rsqrtf(var + 1e-5f);

    const size_t o = (size_t)row * DD;
    out[o + tid]       = __float2bfloat16(d0 * inv * g[tid]       + be[tid]);
    out[o + tid + 128] = __float2bfloat16(d1 * inv * g[tid + 128] + be[tid + 128]);
    out[o + tid + 256] = __float2bfloat16(d2 * inv * g[tid + 256] + be[tid + 256]);
}

// ---------------------------------------------------------------------------
// bf16 GEMM, cp.async 3-stage, DYNAMIC smem. Tile 128x128x32, 8 warps (2x4),
// warp 64x32.
// EPI: 1 +bias->bf16 | 2 +bias,gelu->bf16 | 3 +bias,+res(f32)->f32
//      5 fused gq/gk/gv ->f32 x3
//      7 qkv head-pair stripes: n0 = blockIdx.x*384 + M (M = 128*g),
//        natural bf16 out, Q cols (gc<384) scaled by QSCALE
// ---------------------------------------------------------------------------
__device__ __forceinline__ float gelu_f(float x) {
    float x3 = x * x * x;
    return 0.5f * x * (1.0f + tanhf(0.7978845608028654f * (x + 0.044715f * x3)));
}

#define AS_STR 40
#define BS_STR 136
#define STAGES 3
#define AS_ELEMS (128 * AS_STR)
#define BS_ELEMS (32 * BS_STR)
#define SMEM_GEMM ((STAGES * (AS_ELEMS + BS_ELEMS)) * 2)   // 56832 bytes

template <int EPI, bool CONCAT>
__global__ void __launch_bounds__(256) gemm_bf(
    const __nv_bfloat16* __restrict__ A, const __nv_bfloat16* __restrict__ A2,
    const __nv_bfloat16* __restrict__ Bm, const float* __restrict__ bias,
    const float* __restrict__ res,
    void* __restrict__ out0, void* __restrict__ out1, void* __restrict__ out2,
    int M, int N, int Kd)
{
    extern __shared__ __nv_bfloat16 gsm[];
    __nv_bfloat16* Asb = gsm;
    __nv_bfloat16* Bsb = gsm + STAGES * AS_ELEMS;

    const int tid  = threadIdx.x;
    const int lane = tid & 31;
    const int wid  = tid >> 5;
    const int m0 = blockIdx.y * 128;
    int n0 = blockIdx.x * 128;
    if (EPI == 7) n0 = blockIdx.x * DD + M;   // stripe mapping (M = col offset)

    const __nv_bfloat16* Bp = Bm;
    float* o5 = nullptr;
    if (EPI == 5) {
        int part = n0 / DD;
        Bp = Bm + (size_t)part * DD * DD;
        o5 = part == 0 ? (float*)out0 : part == 1 ? (float*)out1 : (float*)out2;
        n0 -= part * DD;
    }

    const int wm = (wid >> 2) * 64;
    const int wn = (wid & 3) * 32;
    const int r  = lane >> 2;
    const int cq = lane & 3;
    const int lr = lane & 15, lc = lane >> 4;
    const int g8 = lane >> 3, l7 = lane & 7;

    const int lda = CONCAT ? DD : Kd;
    const int arow = tid >> 1, ac = (tid & 1) * 16;
    const int ntile = Kd >> 5;

    auto issue = [&](int kt, int st) {
        int gk0 = kt * 32;
        const __nv_bfloat16* ha = A;
        int cb = gk0;
        if (CONCAT && gk0 >= DD) { ha = A2; cb = gk0 - DD; }
        const __nv_bfloat16* asrc = ha + (size_t)(m0 + arow) * lda + cb + ac;
        unsigned ad = sptr(&Asb[st * AS_ELEMS + arow * AS_STR + ac]);
        cpa16(ad, asrc);
        cpa16(ad + 16, asrc + 8);
        #pragma unroll
        for (int it = 0; it < 2; it++) {
            int c   = tid + it * 256;
            int row = c >> 4;
            int col = (c & 15) * 8;
            cpa16(sptr(&Bsb[st * BS_ELEMS + row * BS_STR + col]),
                  Bp + (size_t)(gk0 + row) * N + n0 + col);
        }
    };

    float acc[4][4][4];
    #pragma unroll
    for (int i = 0; i < 4; i++)
        #pragma unroll
        for (int j = 0; j < 4; j++)
            #pragma unroll
            for (int t = 0; t < 4; t++) acc[i][j][t] = 0.0f;

    issue(0, 0); cp_commit();
    issue(1, 1); cp_commit();

    int st = 0;
    for (int kt = 0; kt < ntile; kt++, st = (st + 1 == STAGES) ? 0 : st + 1) {
        cp_wait<STAGES - 2>();
        __syncthreads();
        if (kt + 2 < ntile) {
            int ns = st + 2; if (ns >= STAGES) ns -= STAGES;
            issue(kt + 2, ns); cp_commit();
        }

        const __nv_bfloat16* As = Asb + st * AS_ELEMS;
        const __nv_bfloat16* Bs = Bsb + st * BS_ELEMS;

        #pragma unroll
        for (int kat = 0; kat < 2; kat++) {
            unsigned a[4][4];
            #pragma unroll
            for (int ma = 0; ma < 4; ma++)
                ldsm_x4(a[ma][0], a[ma][1], a[ma][2], a[ma][3],
                        sptr(&As[(wm + ma * 16 + lr) * AS_STR + kat * 16 + lc * 8]));
            unsigned b[4][2];
            #pragma unroll
            for (int rn = 0; rn < 2; rn++) {
                unsigned r0, r1, r2, r3;
                ldsm_x4_t(r0, r1, r2, r3,
                    sptr(&Bs[(kat * 16 + (g8 & 1) * 8 + l7) * BS_STR
                             + wn + rn * 16 + (g8 >> 1) * 8]));
                b[2 * rn][0] = r0; b[2 * rn][1] = r1;
                b[2 * rn + 1][0] = r2; b[2 * rn + 1][1] = r3;
            }
            #pragma unroll
            for (int ma = 0; ma < 4; ma++)
                #pragma unroll
                for (int na = 0; na < 4; na++)
                    mma_bf16(acc[ma][na], a[ma][0], a[ma][1], a[ma][2], a[ma][3],
                             b[na][0], b[na][1]);
        }
    }

    #pragma unroll
    for (int ma = 0; ma < 4; ma++) {
        #pragma unroll
        for (int half = 0; half < 2; half++) {
            int gm = m0 + wm + ma * 16 + r + 8 * half;
            #pragma unroll
            for (int na = 0; na < 4; na++) {
                int gc = n0 + wn + na * 8 + 2 * cq;
                float v0 = acc[ma][na][2 * half];
                float v1 = acc[ma][na][2 * half + 1];
                if (EPI == 7) {
                    if (gc < DD) { v0 *= QSCALE; v1 *= QSCALE; }
                    *(unsigned*)((__nv_bfloat16*)out0 + (size_t)gm * N + gc) =
                        pack_bf16(v0, v1);
                } else if (EPI == 5) {
                    float2 o; o.x = v0; o.y = v1;
                    *(float2*)(o5 + (size_t)gm * DD + gc) = o;
                } else {
                    v0 += bias[gc]; v1 += bias[gc + 1];
                    if (EPI == 2) { v0 = gelu_f(v0); v1 = gelu_f(v1); }
                    if (EPI == 3) {
                        const float2 rr = *(const float2*)(res + (size_t)gm * N + gc);
                        v0 += rr.x; v1 += rr.y;
                        float2 o; o.x = v0; o.y = v1;
                        *(float2*)((float*)out0 + (size_t)gm * N + gc) = o;
                    } else {
                        *(unsigned*)((__nv_bfloat16*)out0 + (size_t)gm * N + gc) =
                            pack_bf16(v0, v1);
                    }
                }
            }
        }
    }
}

// ---------------------------------------------------------------------------
// bf16 flash attention, chunk-interleaved, no-max softmax (exp2).
// QKV in natural [row][1152] layout. Head-pair group: grid.y in [0,4),
// b = y>>1, h = 2*hpair + (y&1). 256 threads, FQ=128, key tile 64.
// 3-stage cp.async K/V ring, prefetch distance 2, cp_wait<1>.
// ---------------------------------------------------------------------------
#define FQ  128
#define FKT 64
#define FSTR 72
#define FSTAGES 3
#define FL_Q_ELEMS  (FQ * FSTR)
#define FL_KV_ELEMS (FKT * FSTR)
#define FL_BYTES ((FL_Q_ELEMS + FSTAGES * 2 * FL_KV_ELEMS) * 2)   // 73728

__global__ void __launch_bounds__(256) flash_tc(
    const __nv_bfloat16* __restrict__ QKV, __nv_bfloat16* __restrict__ out,
    int hpair)
{
    extern __shared__ __nv_bfloat16 fsm[];
    __nv_bfloat16* Qs = fsm;

    const int tid  = threadIdx.x;
    const int lane = tid & 31;
    const int wid  = tid >> 5;
    const int b  = blockIdx.y >> 1;
    const int h  = 2 * hpair + (blockIdx.y & 1);
    const int q0 = blockIdx.x * FQ;

    const __nv_bfloat16* rowbase = QKV + (size_t)(b * NN) * RSQ + h * DH;
    const __nv_bfloat16* Qp = rowbase;
    const __nv_bfloat16* Kp = rowbase + DD;
    const __nv_bfloat16* Vp = rowbase + 2 * DD;

    const int r  = lane >> 2;
    const int cq = lane & 3;
    const int wq = wid * 16;
    const int lr = lane & 15, lc = lane >> 4;
    const int g8 = lane >> 3, l7 = lane & 7;

    auto issueKV = [&](int k0, int stg) {
        __nv_bfloat16* Kst = fsm + FL_Q_ELEMS + (size_t)stg * 2 * FL_KV_ELEMS;
        __nv_bfloat16* Vst = Kst + FL_KV_ELEMS;
        #pragma unroll
        for (int it = 0; it < 2; it++) {
            int c   = tid + it * 256;
            int row = c >> 3;
            int c8  = (c & 7) * 8;
            cpa16(sptr(&Kst[row * FSTR + c8]), Kp + (size_t)(k0 + row) * RSQ + c8);
            cpa16(sptr(&Vst[row * FSTR + c8]), Vp + (size_t)(k0 + row) * RSQ + c8);
        }
    };

    issueKV(0, 0); cp_commit();
    issueKV(FKT, 1); cp_commit();

    #pragma unroll
    for (int it = 0; it < 4; it++) {
        int id  = tid + it * 256;
        int row = id >> 3;
        int c8  = (id & 7) << 3;
        *(uint4*)&Qs[row * FSTR + c8] =
            *(const uint4*)(Qp + (size_t)(q0 + row) * RSQ + c8);
    }
    __syncthreads();

    unsigned qa[4][4];
    #pragma unroll
    for (int kat = 0; kat < 4; kat++)
        ldsm_x4(qa[kat][0], qa[kat][1], qa[kat][2], qa[kat][3],
                sptr(&Qs[(wq + lr) * FSTR + kat * 16 + lc * 8]));

    float O[8][4];
    float lrow[2];
    lrow[0] = 0.0f; lrow[1] = 0.0f;
    #pragma unroll
    for (int j = 0; j < 8; j++)
        #pragma unroll
        for (int t = 0; t < 4; t++) O[j][t] = 0.0f;

    const int NKT = NN / FKT;
    for (int kt = 0; kt < NKT; kt++) {
        cp_wait<1>();
        __syncthreads();
        const int stg = kt % FSTAGES;
        if (kt + 2 < NKT) {
            int ns = stg + 2; if (ns >= FSTAGES) ns -= FSTAGES;
            issueKV((kt + 2) * FKT, ns); cp_commit();
        }

        __nv_bfloat16* Ks = fsm + FL_Q_ELEMS + (size_t)stg * 2 * FL_KV_ELEMS;
        __nv_bfloat16* Vs = Ks + FL_KV_ELEMS;

        #pragma unroll
        for (int kc = 0; kc < 4; kc++) {
            float s0[4] = {0.0f, 0.0f, 0.0f, 0.0f};
            float s1[4] = {0.0f, 0.0f, 0.0f, 0.0f};
            #pragma unroll
            for (int kat = 0; kat < 4; kat++) {
                unsigned b0, b1, b2, b3;
                ldsm_x4(b0, b1, b2, b3,
                    sptr(&Ks[(kc * 16 + (g8 >> 1) * 8 + l7) * FSTR
                             + kat * 16 + (g8 & 1) * 8]));
                mma_bf16(s0, qa[kat][0], qa[kat][1], qa[kat][2], qa[kat][3], b0, b1);
                mma_bf16(s1, qa[kat][0], qa[kat][1], qa[kat][2], qa[kat][3], b2, b3);
            }

            unsigned pa[4];
            {
                float p0 = ex2f(s0[0]);
                float p1 = ex2f(s0[1]);
                float p2 = ex2f(s0[2]);
                float p3 = ex2f(s0[3]);
                lrow[0] += p0 + p1;
                lrow[1] += p2 + p3;
                pa[0] = pack_bf16(p0, p1);
                pa[1] = pack_bf16(p2, p3);
                float q0f = ex2f(s1[0]);
                float q1f = ex2f(s1[1]);
                float q2f = ex2f(s1[2]);
                float q3f = ex2f(s1[3]);
                lrow[0] += q0f + q1f;
                lrow[1] += q2f + q3f;
                pa[2] = pack_bf16(q0f, q1f);
                pa[3] = pack_bf16(q2f, q3f);
            }

            #pragma unroll
            for (int nd = 0; nd < 4; nd++) {
                unsigned b0, b1, b2, b3;
                ldsm_x4_t(b0, b1, b2, b3,
                    sptr(&Vs[(kc * 16 + (g8 & 1) * 8 + l7) * FSTR
                             + nd * 16 + (g8 >> 1) * 8]));
                mma_bf16(O[2 * nd],     pa[0], pa[1], pa[2], pa[3], b0, b1);
                mma_bf16(O[2 * nd + 1], pa[0], pa[1], pa[2], pa[3], b2, b3);
            }
        }
    }

    #pragma unroll
    for (int half = 0; half < 2; half++) {
        float lf = lrow[half];
        lf += __shfl_xor_sync(0xffffffffu, lf, 1);
        lf += __shfl_xor_sync(0xffffffffu, lf, 2);
        float inv = 1.0f / lf;
        const int gq = q0 + wq + r + 8 * half;
        const int f0 = 2 * half, f1 = f0 + 1;
        #pragma unroll
        for (int na = 0; na < 8; na++) {
            *(unsigned*)(out + ((size_t)(b * NN + gq)) * DD
                               + h * DH + na * 8 + 2 * cq) =
                pack_bf16(O[na][f0] * inv, O[na][f1] * inv);
        }
    }
}

// ---------------------------------------------------------------------------
// kNN top-8 (matches jax: value = (sq_q + sq_m) - 2*dot, smallest-8, stable)
// ---------------------------------------------------------------------------
__global__ void __launch_bounds__(256) knn_kernel(
    const float* __restrict__ coords, int* __restrict__ out)
{
    __shared__ float xs[NN], ys[NN], zs[NN];
    const int b = blockIdx.y;
    const int q = blockIdx.x * 256 + threadIdx.x;
    const float* cb = coords + (size_t)b * NN * 3;

    for (int i = threadIdx.x; i < NN; i += 256) {
        xs[i] = cb[i * 3 + 0];
        ys[i] = cb[i * 3 + 1];
        zs[i] = cb[i * 3 + 2];
    }
    __syncthreads();

    const float qx = xs[q], qy = ys[q], qz = zs[q];
    const float sqq = qx * qx + qy * qy + qz * qz;

    float bd[KNN_K];
    int   bi[KNN_K];
    #pragma unroll
    for (int i = 0; i < KNN_K; i++) { bd[i] = 3.4e38f; bi[i] = 0; }
    float worst = 3.4e38f;

    for (int mI = 0; mI < NN; mI++) {
        float x = xs[mI], y = ys[mI], z = zs[mI];
        float sqm = x * x + y * y + z * z;
        float dot = qx * x + qy * y + qz * z;
        float v = (sqq + sqm) - 2.0f * dot;
        if (v < worst) {
            int j = KNN_K - 1;
            while (j > 0 && bd[j - 1] > v) {
                bd[j] = bd[j - 1];
                bi[j] = bi[j - 1];
                j--;
            }
            bd[j] = v;
            bi[j] = mI;
            worst = bd[KNN_K - 1];
        }
    }

    int* orow = out + ((size_t)(b * NN + q)) * KNN_K;
    #pragma unroll
    for (int i = 0; i < KNN_K; i++) orow[i] = bi[i];
}

// ---------------------------------------------------------------------------
// Graph neighbor attention: one block per (b,n), 128 threads, bf16 out
// ---------------------------------------------------------------------------
__global__ void __launch_bounds__(128) graphattn_kernel(
    const float* __restrict__ gq, const float* __restrict__ gk,
    const float* __restrict__ gv, const int* __restrict__ knn,
    __nv_bfloat16* __restrict__ out)
{
    const int blk  = blockIdx.x;
    const int b    = blk >> 12;
    const int tid  = threadIdx.x;
    const int wid  = tid >> 5;
    const int lane = tid & 31;

    __shared__ float ssc[KNN_K];
    __shared__ int   sidx[KNN_K];
    if (tid < KNN_K) sidx[tid] = knn[(size_t)blk * KNN_K + tid];
    __syncthreads();

    const float* qr = gq + (size_t)blk * DD;

    #pragma unroll
    for (int t = 0; t < 2; t++) {
        int kk = wid + t * 4;
        const float* kr = gk + ((size_t)(b * NN + sidx[kk])) * DD;
        float dot = 0.0f;
        for (int c = lane; c < DD; c += 32) dot = fmaf(qr[c], kr[c], dot);
        #pragma unroll
        for (int off = 16; off; off >>= 1)
            dot += __shfl_xor_sync(0xffffffffu, dot, off);
        if (lane == 0) ssc[kk] = dot;
    }
    __syncthreads();

    float sc[KNN_K];
    float mx = -3.0e38f;
    #pragma unroll
    for (int kk = 0; kk < KNN_K; kk++) {
        sc[kk] = ssc[kk] * 0.05103103630798288f;
        mx = fmaxf(mx, sc[kk]);
    }
    float sum = 0.0f;
    #pragma unroll
    for (int kk = 0; kk < KNN_K; kk++) { sc[kk] = __expf(sc[kk] - mx); sum += sc[kk]; }
    float inv = 1.0f / sum;

    float o0 = 0.0f, o1 = 0.0f, o2 = 0.0f;
    #pragma unroll
    for (int kk = 0; kk < KNN_K; kk++) {
        const float* vr = gv + ((size_t)(b * NN + sidx[kk])) * DD;
        float a = sc[kk] * inv;
        o0 = fmaf(a, vr[tid],       o0);
        o1 = fmaf(a, vr[tid + 128], o1);
        o2 = fmaf(a, vr[tid + 256], o2);
    }
    __nv_bfloat16* orow = out + (size_t)blk * DD;
    orow[tid]       = __float2bfloat16(o0);
    orow[tid + 128] = __float2bfloat16(o1);
    orow[tid + 256] = __float2bfloat16(o2);
}

// ---------------------------------------------------------------------------
// Host launcher — 4 streams ONLY (5th stream trips harness alloc guard).
// qkv runs as 3 stripe launches; flash group g starts as soon as stripe g
// lands: group 0 on sKnn (idle after kNN), group 1 on sPre (idle after
// precompute), group 2 on main. Groups co-run -> full aggregate wave.
// ---------------------------------------------------------------------------
extern "C" void kernel_launch(void* const* d_in, const int* in_sizes, int n_in,
                              void* d_out, int out_size)
{
    const float* coords     = (const float*)d_in[0];
    const float* features   = (const float*)d_in[1];
    const float* ln1_g      = (const float*)d_in[2];
    const float* ln1_b      = (const float*)d_in[3];
    const float* w_qkv      = (const float*)d_in[4];
    const float* w_attn_out = (const float*)d_in[5];
    const float* b_attn_out = (const float*)d_in[6];
    const float* w_gq       = (const float*)d_in[7];
    const float* w_gk       = (const float*)d_in[8];
    const float* w_gv       = (const float*)d_in[9];
    const float* w_merge    = (const float*)d_in[10];
    const float* b_merge    = (const float*)d_in[11];
    const float* ln2_g      = (const float*)d_in[12];
    const float* ln2_b      = (const float*)d_in[13];
    const float* w_ff1      = (const float*)d_in[14];
    const float* b_ff1      = (const float*)d_in[15];
    const float* w_ff2      = (const float*)d_in[16];
    const float* b_ff2      = (const float*)d_in[17];
    float* outp = (float*)d_out;

    __nv_bfloat16 *NF, *QKVb, *ATTN, *GEOM, *H2, *G1, *WB, *WM2;
    float *GQ, *GK, *GV, *F2, *BC, *ZB;
    int* KNNp;
    cudaGetSymbolAddress((void**)&NF,    g_NF);
    cudaGetSymbolAddress((void**)&QKVb,  g_QKV);
    cudaGetSymbolAddress((void**)&GQ,    g_GQ);
    cudaGetSymbolAddress((void**)&GK,    g_GK);
    cudaGetSymbolAddress((void**)&GV,    g_GV);
    cudaGetSymbolAddress((void**)&ATTN,  g_ATTN);
    cudaGetSymbolAddress((void**)&GEOM,  g_GEOM);
    cudaGetSymbolAddress((void**)&F2,    g_F2);
    cudaGetSymbolAddress((void**)&H2,    g_H2);
    cudaGetSymbolAddress((void**)&G1,    g_G1);
    cudaGetSymbolAddress((void**)&WB,    g_WB);
    cudaGetSymbolAddress((void**)&WM2,   g_WM2);
    cudaGetSymbolAddress((void**)&BC,    g_BC);
    cudaGetSymbolAddress((void**)&ZB,    g_ZB);
    cudaGetSymbolAddress((void**)&KNNp,  g_KNN);

    cudaFuncSetAttribute(gemm_bf<7, false>,
        cudaFuncAttributeMaxDynamicSharedMemorySize, SMEM_GEMM);
    cudaFuncSetAttribute(gemm_bf<5, false>,
        cudaFuncAttributeMaxDynamicSharedMemorySize, SMEM_GEMM);
    cudaFuncSetAttribute(gemm_bf<1, false>,
        cudaFuncAttributeMaxDynamicSharedMemorySize, SMEM_GEMM);
    cudaFuncSetAttribute(gemm_bf<2, false>,
        cudaFuncAttributeMaxDynamicSharedMemorySize, SMEM_GEMM);
    cudaFuncSetAttribute(gemm_bf<3, false>,
        cudaFuncAttributeMaxDynamicSharedMemorySize, SMEM_GEMM);
    cudaFuncSetAttribute(gemm_bf<3, true>,
        cudaFuncAttributeMaxDynamicSharedMemorySize, SMEM_GEMM);
    cudaFuncSetAttribute(flash_tc,
        cudaFuncAttributeMaxDynamicSharedMemorySize, FL_BYTES);

    // exactly 4 streams (5 trips the harness's device-memory guard)
    cudaStream_t sGeo, sKnn, sPre;
    cudaStreamCreateWithFlags(&sGeo, cudaStreamNonBlocking);
    cudaStreamCreateWithFlags(&sKnn, cudaStreamNonBlocking);
    cudaStreamCreateWithFlags(&sPre, cudaStreamNonBlocking);
    cudaEvent_t evRoot, evW, evLn1, evKnn, evGeom, evPre;
    cudaEvent_t evQ0, evQ1, evF0, evF1;
    cudaEventCreateWithFlags(&evRoot, cudaEventDisableTiming);
    cudaEventCreateWithFlags(&evW,    cudaEventDisableTiming);
    cudaEventCreateWithFlags(&evLn1,  cudaEventDisableTiming);
    cudaEventCreateWithFlags(&evKnn,  cudaEventDisableTiming);
    cudaEventCreateWithFlags(&evGeom, cudaEventDisableTiming);
    cudaEventCreateWithFlags(&evPre,  cudaEventDisableTiming);
    cudaEventCreateWithFlags(&evQ0,   cudaEventDisableTiming);
    cudaEventCreateWithFlags(&evQ1,   cudaEventDisableTiming);
    cudaEventCreateWithFlags(&evF0,   cudaEventDisableTiming);
    cudaEventCreateWithFlags(&evF1,   cudaEventDisableTiming);

    // ---- root fork ----
    cudaEventRecord(evRoot, 0);
    cudaStreamWaitEvent(sKnn, evRoot, 0);
    knn_kernel<<<dim3(NN / 256, BB), 256, 0, sKnn>>>(coords, KNNp);
    cudaEventRecord(evKnn, sKnn);

    cudaStreamWaitEvent(sGeo, evRoot, 0);
    ln_kernel<<<ROWS, 128, 0, sGeo>>>(features, ln1_g, ln1_b, NF);
    cudaEventRecord(evLn1, sGeo);

    // ---- main: pack weights ----
    wcvt_kernel<<<(TOTW / 4 + 255) / 256, 256>>>(
        w_qkv, w_gq, w_gk, w_gv, w_attn_out, w_merge, w_ff1, w_ff2, WB);
    cudaEventRecord(evW, 0);

    // ---- precompute stream: fused merge weight + bias ----
    cudaStreamWaitEvent(sPre, evW, 0);
    gemm_bf<1, false><<<dim3(3, 3), 256, SMEM_GEMM, sPre>>>(
        WB + OFF_ATT, nullptr, WB + OFF_MRG, ZB, nullptr,
        WM2, nullptr, nullptr, DD, DD, DD);
    wcopy_kernel<<<(DD * DD / 8 + 255) / 256, 256, 0, sPre>>>(
        WB + OFF_MRG + DD * DD, WM2 + DD * DD);
    biascomb_kernel<<<1, DD, 0, sPre>>>(b_attn_out, w_merge, b_merge, BC);
    cudaEventRecord(evPre, sPre);

    // ---- geometry branch (sGeo) ----
    cudaStreamWaitEvent(sGeo, evW, 0);
    gemm_bf<5, false><<<dim3(1152 / 128, ROWS / 128), 256, SMEM_GEMM, sGeo>>>(
        NF, nullptr, WB + OFF_GQ, nullptr, nullptr,
        GQ, GK, GV, ROWS, DD, DD);
    cudaStreamWaitEvent(sGeo, evKnn, 0);
    graphattn_kernel<<<ROWS, 128, 0, sGeo>>>(GQ, GK, GV, KNNp, GEOM);
    cudaEventRecord(evGeom, sGeo);

    // ---- attention: qkv stripes on main; flash groups fork as ready ----
    cudaStreamWaitEvent(0, evLn1, 0);
    gemm_bf<7, false><<<dim3(3, ROWS / 128), 256, SMEM_GEMM>>>(
        NF, nullptr, WB + OFF_QKV, nullptr, nullptr,
        QKVb, nullptr, nullptr, /*M=colOff*/ 0, RSQ, DD);
    cudaEventRecord(evQ0, 0);
    gemm_bf<7, false><<<dim3(3, ROWS / 128), 256, SMEM_GEMM>>>(
        NF, nullptr, WB + OFF_QKV, nullptr, nullptr,
        QKVb, nullptr, nullptr, 128, RSQ, DD);
    cudaEventRecord(evQ1, 0);
    gemm_bf<7, false><<<dim3(3, ROWS / 128), 256, SMEM_GEMM>>>(
        NF, nullptr, WB + OFF_QKV, nullptr, nullptr,
        QKVb, nullptr, nullptr, 256, RSQ, DD);

    // flash group 0 (heads 0,1) on sKnn after stripe 0 (kNN long done)
    cudaStreamWaitEvent(sKnn, evQ0, 0);
    flash_tc<<<dim3(NN / FQ, 4), 256, FL_BYTES, sKnn>>>(QKVb, ATTN, 0);
    cudaEventRecord(evF0, sKnn);
    // flash group 1 (heads 2,3) on sPre after stripe 1 (precompute done)
    cudaStreamWaitEvent(sPre, evQ1, 0);
    flash_tc<<<dim3(NN / FQ, 4), 256, FL_BYTES, sPre>>>(QKVb, ATTN, 1);
    cudaEventRecord(evF1, sPre);
    // flash group 2 (heads 4,5) on main after stripe 2
    flash_tc<<<dim3(NN / FQ, 4), 256, FL_BYTES>>>(QKVb, ATTN, 2);

    // ---- join + fused merge + serial tail (whole ROWS) ----
    cudaStreamWaitEvent(0, evF0, 0);
    cudaStreamWaitEvent(0, evF1, 0);
    cudaStreamWaitEvent(0, evGeom, 0);
    cudaStreamWaitEvent(0, evPre, 0);
    gemm_bf<3, true><<<dim3(DD / 128, ROWS / 128), 256, SMEM_GEMM>>>(
        ATTN, GEOM, WM2, BC, features,
        F2, nullptr, nullptr, ROWS, DD, 2 * DD);
    ln_kernel<<<ROWS, 128>>>(F2, ln2_g, ln2_b, H2);
    gemm_bf<2, false><<<dim3(2 * DD / 128, ROWS / 128), 256, SMEM_GEMM>>>(
        H2, nullptr, WB + OFF_FF1, b_ff1, nullptr,
        G1, nullptr, nullptr, ROWS, 2 * DD, DD);
    gemm_bf<3, false><<<dim3(DD / 128, ROWS / 128), 256, SMEM_GEMM>>>(
        G1, nullptr, WB + OFF_FF2, b_ff2, F2,
        outp, nullptr, nullptr, ROWS, DD, 2 * DD);

    cudaEventDestroy(evRoot);
    cudaEventDestroy(evW);
    cudaEventDestroy(evLn1);
    cudaEventDestroy(evKnn);
    cudaEventDestroy(evGeom);
    cudaEventDestroy(evPre);
    cudaEventDestroy(evQ0);
    cudaEventDestroy(evQ1);
    cudaEventDestroy(evF0);
    cudaEventDestroy(evF1);
    cudaStreamDestroy(sGeo);
    cudaStreamDestroy(sKnn);
    cudaStreamDestroy(sPre);
}

// round 14
// speedup vs baseline: 1.1671x; 1.1671x over previous
#include <cuda_runtime.h>
#include <cuda_bf16.h>
#include <math.h>

// ---------------------------------------------------------------------------
// Problem constants
// ---------------------------------------------------------------------------
#define BB   2
#define NN   4096
#define DD   384
#define HH   6
#define DH   64
#define ROWS (BB * NN)          // 8192
#define KNN_K 8
#define RSQ  (3 * DD)           // 1152, QKV row stride

// packed bf16 weight buffer offsets
#define OFF_QKV 0
#define OFF_GQ  442368
#define OFF_ATT 884736
#define OFF_MRG 1032192
#define OFF_FF1 1327104
#define OFF_FF2 1622016
#define TOTW    1916928

// Q pre-scale: (1/8) * log2(e)  -> softmax via ex2.approx
#define QSCALE 0.18033688011112042f

// ---------------------------------------------------------------------------
// Scratch (global device arrays; no allocations anywhere)
// ---------------------------------------------------------------------------
__device__ __nv_bfloat16 g_NF   [ROWS * DD];
__device__ __nv_bfloat16 g_QKV  [ROWS * RSQ];      // [row][q|k|v x 384]
__device__ float         g_GQ   [ROWS * DD];
__device__ float         g_GK   [ROWS * DD];
__device__ float         g_GV   [ROWS * DD];
__device__ __nv_bfloat16 g_ATTN [ROWS * DD];
__device__ __nv_bfloat16 g_GEOM [ROWS * DD];
__device__ float         g_F2   [ROWS * DD];
__device__ __nv_bfloat16 g_H2   [ROWS * DD];
__device__ __nv_bfloat16 g_G1   [ROWS * 2 * DD];
__device__ __nv_bfloat16 g_WB   [TOTW];
__device__ __nv_bfloat16 g_WM2  [2 * DD * DD];     // fused attn-out x merge
__device__ float         g_BC   [DD];              // combined merge bias
__device__ float         g_ZB   [DD];              // zeros (static init)
__device__ int           g_KNN  [BB * NN * KNN_K];

// ---------------------------------------------------------------------------
// asm helpers
// ---------------------------------------------------------------------------
__device__ __forceinline__ unsigned sptr(const void* p) {
    return (unsigned)__cvta_generic_to_shared(p);
}
__device__ __forceinline__ void cpa16(unsigned dst, const void* src) {
    asm volatile("cp.async.cg.shared.global [%0], [%1], 16;" :: "r"(dst), "l"(src));
}
__device__ __forceinline__ void cp_commit() {
    asm volatile("cp.async.commit_group;" ::: "memory");
}
template <int N>
__device__ __forceinline__ void cp_wait() {
    asm volatile("cp.async.wait_group %0;" :: "n"(N) : "memory");
}
__device__ __forceinline__ void ldsm_x4(unsigned& r0, unsigned& r1,
                                        unsigned& r2, unsigned& r3, unsigned a) {
    asm volatile("ldmatrix.sync.aligned.m8n8.x4.shared.b16 {%0,%1,%2,%3}, [%4];"
        : "=r"(r0), "=r"(r1), "=r"(r2), "=r"(r3) : "r"(a));
}
__device__ __forceinline__ void ldsm_x4_t(unsigned& r0, unsigned& r1,
                                          unsigned& r2, unsigned& r3, unsigned a) {
    asm volatile("ldmatrix.sync.aligned.m8n8.x4.trans.shared.b16 {%0,%1,%2,%3}, [%4];"
        : "=r"(r0), "=r"(r1), "=r"(r2), "=r"(r3) : "r"(a));
}
__device__ __forceinline__ void mma_bf16(float* c,
    unsigned a0, unsigned a1, unsigned a2, unsigned a3, unsigned b0, unsigned b1)
{
    asm volatile(
        "mma.sync.aligned.m16n8k16.row.col.f32.bf16.bf16.f32 "
        "{%0,%1,%2,%3}, {%4,%5,%6,%7}, {%8,%9}, {%0,%1,%2,%3};"
        : "+f"(c[0]), "+f"(c[1]), "+f"(c[2]), "+f"(c[3])
        : "r"(a0), "r"(a1), "r"(a2), "r"(a3), "r"(b0), "r"(b1));
}
__device__ __forceinline__ unsigned pack_bf16(float lo, float hi) {
    unsigned r;
    asm("cvt.rn.bf16x2.f32 %0, %1, %2;" : "=r"(r) : "f"(hi), "f"(lo));
    return r;
}
__device__ __forceinline__ float ex2f(float x) {
    float r;
    asm("ex2.approx.f32 %0, %1;" : "=f"(r) : "f"(x));
    return r;
}

// ---------------------------------------------------------------------------
// Weight conversion: 8 fp32 matrices -> one packed bf16 buffer
// ---------------------------------------------------------------------------
__global__ void __launch_bounds__(256) wcvt_kernel(
    const float* __restrict__ a0, const float* __restrict__ a1,
    const float* __restrict__ a2, const float* __restrict__ a3,
    const float* __restrict__ a4, const float* __restrict__ a5,
    const float* __restrict__ a6, const float* __restrict__ a7,
    __nv_bfloat16* __restrict__ o)
{
    int i4 = (blockIdx.x * 256 + threadIdx.x) * 4;
    if (i4 >= TOTW) return;
    const float* src; int loc;
    if      (i4 < OFF_GQ)           { src = a0; loc = i4; }
    else if (i4 < OFF_GQ + 147456)  { src = a1; loc = i4 - OFF_GQ; }
    else if (i4 < OFF_GQ + 294912)  { src = a2; loc = i4 - OFF_GQ - 147456; }
    else if (i4 < OFF_ATT)          { src = a3; loc = i4 - OFF_GQ - 294912; }
    else if (i4 < OFF_MRG)          { src = a4; loc = i4 - OFF_ATT; }
    else if (i4 < OFF_FF1)          { src = a5; loc = i4 - OFF_MRG; }
    else if (i4 < OFF_FF2)          { src = a6; loc = i4 - OFF_FF1; }
    else                            { src = a7; loc = i4 - OFF_FF2; }
    float4 v = *(const float4*)(src + loc);
    uint2 u;
    u.x = pack_bf16(v.x, v.y);
    u.y = pack_bf16(v.z, v.w);
    *(uint2*)(o + i4) = u;
}

// copy bottom half of merge weight (bf16) into WM2 bottom
__global__ void __launch_bounds__(256) wcopy_kernel(
    const __nv_bfloat16* __restrict__ src, __nv_bfloat16* __restrict__ dst)
{
    int i8 = (blockIdx.x * 256 + threadIdx.x) * 8;
    if (i8 < DD * DD)
        *(uint4*)(dst + i8) = *(const uint4*)(src + i8);
}

// combined merge bias: bc[j] = sum_i b_ao[i] * wm[i*DD+j] + b_merge[j]
__global__ void __launch_bounds__(DD) biascomb_kernel(
    const float* __restrict__ b_ao, const float* __restrict__ wm,
    const float* __restrict__ b_merge, float* __restrict__ bc)
{
    int j = threadIdx.x;
    float s = b_merge[j];
    for (int i = 0; i < DD; i++) s = fmaf(b_ao[i], wm[i * DD + j], s);
    bc[j] = s;
}

// ---------------------------------------------------------------------------
// LayerNorm: one block per row, 128 threads, bf16 output
// ---------------------------------------------------------------------------
__global__ void __launch_bounds__(128) ln_kernel(
    const float* __restrict__ x, const float* __restrict__ g,
    const float* __restrict__ be, __nv_bfloat16* __restrict__ out)
{
    const int row = blockIdx.x;
    const int tid = threadIdx.x;
    const float* xr = x + (size_t)row * DD;

    float v0 = xr[tid], v1 = xr[tid + 128], v2 = xr[tid + 256];

    __shared__ float red[4];
    float s = v0 + v1 + v2;
    #pragma unroll
    for (int off = 16; off; off >>= 1) s += __shfl_xor_sync(0xffffffffu, s, off);
    if ((tid & 31) == 0) red[tid >> 5] = s;
    __syncthreads();
    float mean = (red[0] + red[1] + red[2] + red[3]) * (1.0f / 384.0f);

    float d0 = v0 - mean, d1 = v1 - mean, d2 = v2 - mean;
    float sq = d0 * d0 + d1 * d1 + d2 * d2;
    #pragma unroll
    for (int off = 16; off; off >>= 1) sq += __shfl_xor_sync(0xffffffffu, sq, off);
    __syncthreads();
    if ((tid & 31) == 0) red[tid >> 5] = sq;
    __syncthreads();
    float var = (red[0] + red[1] + red[2] + red[3]) * (1.0f / 384.0f);
    float inv = rsqrtf(var + 1e-5f);

    const size_t o = (size_t)row * DD;
    out[o + tid]       = __float2bfloat16(d0 * inv * g[tid]       + be[tid]);
    out[o + tid + 128] = __float2bfloat16(d1 * inv * g[tid + 128] + be[tid + 128]);
    out[o + tid + 256] = __float2bfloat16(d2 * inv * g[tid + 256] + be[tid + 256]);
}

// ---------------------------------------------------------------------------
// bf16 GEMM, cp.async 3-stage, DYNAMIC smem. Tile 128x128x32, 8 warps (2x4),
// warp 64x32.
// EPI: 1 +bias->bf16 | 2 +bias,gelu->bf16 | 3 +bias,+res(f32)->f32
//      5 fused gq/gk/gv ->f32 x3 | 7 natural bf16, cols<384 scaled by QSCALE
// ---------------------------------------------------------------------------
__device__ __forceinline__ float gelu_f(float x) {
    float x3 = x * x * x;
    return 0.5f * x * (1.0f + tanhf(0.7978845608028654f * (x + 0.044715f * x3)));
}

#define AS_STR 40
#define BS_STR 136
#define STAGES 3
#define AS_ELEMS (128 * AS_STR)
#define BS_ELEMS (32 * BS_STR)
#define SMEM_GEMM ((STAGES * (AS_ELEMS + BS_ELEMS)) * 2)   // 56832 bytes

template <int EPI, bool CONCAT>
__global__ void __launch_bounds__(256) gemm_bf(
    const __nv_bfloat16* __restrict__ A, const __nv_bfloat16* __restrict__ A2,
    const __nv_bfloat16* __restrict__ Bm, const float* __restrict__ bias,
    const float* __restrict__ res,
    void* __restrict__ out0, void* __restrict__ out1, void* __restrict__ out2,
    int M, int N, int Kd)
{
    extern __shared__ __nv_bfloat16 gsm[];
    __nv_bfloat16* Asb = gsm;
    __nv_bfloat16* Bsb = gsm + STAGES * AS_ELEMS;

    const int tid  = threadIdx.x;
    const int lane = tid & 31;
    const int wid  = tid >> 5;
    const int m0 = blockIdx.y * 128;
    int n0 = blockIdx.x * 128;

    const __nv_bfloat16* Bp = Bm;
    float* o5 = nullptr;
    if (EPI == 5) {
        int part = n0 / DD;
        Bp = Bm + (size_t)part * DD * DD;
        o5 = part == 0 ? (float*)out0 : part == 1 ? (float*)out1 : (float*)out2;
        n0 -= part * DD;
    }

    const int wm = (wid >> 2) * 64;
    const int wn = (wid & 3) * 32;
    const int r  = lane >> 2;
    const int cq = lane & 3;
    const int lr = lane & 15, lc = lane >> 4;
    const int g8 = lane >> 3, l7 = lane & 7;

    const int lda = CONCAT ? DD : Kd;
    const int arow = tid >> 1, ac = (tid & 1) * 16;
    const int ntile = Kd >> 5;

    auto issue = [&](int kt, int st) {
        int gk0 = kt * 32;
        const __nv_bfloat16* ha = A;
        int cb = gk0;
        if (CONCAT && gk0 >= DD) { ha = A2; cb = gk0 - DD; }
        const __nv_bfloat16* asrc = ha + (size_t)(m0 + arow) * lda + cb + ac;
        unsigned ad = sptr(&Asb[st * AS_ELEMS + arow * AS_STR + ac]);
        cpa16(ad, asrc);
        cpa16(ad + 16, asrc + 8);
        #pragma unroll
        for (int it = 0; it < 2; it++) {
            int c   = tid + it * 256;
            int row = c >> 4;
            int col = (c & 15) * 8;
            cpa16(sptr(&Bsb[st * BS_ELEMS + row * BS_STR + col]),
                  Bp + (size_t)(gk0 + row) * N + n0 + col);
        }
    };

    float acc[4][4][4];
    #pragma unroll
    for (int i = 0; i < 4; i++)
        #pragma unroll
        for (int j = 0; j < 4; j++)
            #pragma unroll
            for (int t = 0; t < 4; t++) acc[i][j][t] = 0.0f;

    issue(0, 0); cp_commit();
    issue(1, 1); cp_commit();

    int st = 0;
    for (int kt = 0; kt < ntile; kt++, st = (st + 1 == STAGES) ? 0 : st + 1) {
        cp_wait<STAGES - 2>();
        __syncthreads();
        if (kt + 2 < ntile) {
            int ns = st + 2; if (ns >= STAGES) ns -= STAGES;
            issue(kt + 2, ns); cp_commit();
        }

        const __nv_bfloat16* As = Asb + st * AS_ELEMS;
        const __nv_bfloat16* Bs = Bsb + st * BS_ELEMS;

        #pragma unroll
        for (int kat = 0; kat < 2; kat++) {
            unsigned a[4][4];
            #pragma unroll
            for (int ma = 0; ma < 4; ma++)
                ldsm_x4(a[ma][0], a[ma][1], a[ma][2], a[ma][3],
                        sptr(&As[(wm + ma * 16 + lr) * AS_STR + kat * 16 + lc * 8]));
            unsigned b[4][2];
            #pragma unroll
            for (int rn = 0; rn < 2; rn++) {
                unsigned r0, r1, r2, r3;
                ldsm_x4_t(r0, r1, r2, r3,
                    sptr(&Bs[(kat * 16 + (g8 & 1) * 8 + l7) * BS_STR
                             + wn + rn * 16 + (g8 >> 1) * 8]));
                b[2 * rn][0] = r0; b[2 * rn][1] = r1;
                b[2 * rn + 1][0] = r2; b[2 * rn + 1][1] = r3;
            }
            #pragma unroll
            for (int ma = 0; ma < 4; ma++)
                #pragma unroll
                for (int na = 0; na < 4; na++)
                    mma_bf16(acc[ma][na], a[ma][0], a[ma][1], a[ma][2], a[ma][3],
                             b[na][0], b[na][1]);
        }
    }

    #pragma unroll
    for (int ma = 0; ma < 4; ma++) {
        #pragma unroll
        for (int half = 0; half < 2; half++) {
            int gm = m0 + wm + ma * 16 + r + 8 * half;
            #pragma unroll
            for (int na = 0; na < 4; na++) {
                int gc = n0 + wn + na * 8 + 2 * cq;
                float v0 = acc[ma][na][2 * half];
                float v1 = acc[ma][na][2 * half + 1];
                if (EPI == 7) {
                    if (gc < DD) { v0 *= QSCALE; v1 *= QSCALE; }
                    *(unsigned*)((__nv_bfloat16*)out0 + (size_t)gm * N + gc) =
                        pack_bf16(v0, v1);
                } else if (EPI == 5) {
                    float2 o; o.x = v0; o.y = v1;
                    *(float2*)(o5 + (size_t)gm * DD + gc) = o;
                } else {
                    v0 += bias[gc]; v1 += bias[gc + 1];
                    if (EPI == 2) { v0 = gelu_f(v0); v1 = gelu_f(v1); }
                    if (EPI == 3) {
                        const float2 rr = *(const float2*)(res + (size_t)gm * N + gc);
                        v0 += rr.x; v1 += rr.y;
                        float2 o; o.x = v0; o.y = v1;
                        *(float2*)((float*)out0 + (size_t)gm * N + gc) = o;
                    } else {
                        *(unsigned*)((__nv_bfloat16*)out0 + (size_t)gm * N + gc) =
                            pack_bf16(v0, v1);
                    }
                }
            }
        }
    }
}

// ---------------------------------------------------------------------------
// bf16 flash attention, chunk-interleaved, no-max softmax (exp2).
// QKV in natural [row][1152] layout; head slice via column offset.
// 256 threads (8 warps), warp = 16 q-rows, FQ=128, key tile 64.
// 3-stage cp.async K/V ring, prefetch distance 2, cp_wait<1>.
// ---------------------------------------------------------------------------
#define FQ  128
#define FKT 64
#define FSTR 72
#define FSTAGES 3
#define FL_Q_ELEMS  (FQ * FSTR)
#define FL_KV_ELEMS (FKT * FSTR)
#define FL_BYTES ((FL_Q_ELEMS + FSTAGES * 2 * FL_KV_ELEMS) * 2)   // 73728

__global__ void __launch_bounds__(256) flash_tc(
    const __nv_bfloat16* __restrict__ QKV, __nv_bfloat16* __restrict__ out)
{
    extern __shared__ __nv_bfloat16 fsm[];
    __nv_bfloat16* Qs = fsm;

    const int tid  = threadIdx.x;
    const int lane = tid & 31;
    const int wid  = tid >> 5;
    const int bh = blockIdx.y;
    const int b  = bh / HH;
    const int h  = bh - b * HH;
    const int q0 = blockIdx.x * FQ;

    const __nv_bfloat16* rowbase = QKV + (size_t)(b * NN) * RSQ + h * DH;
    const __nv_bfloat16* Qp = rowbase;                 // cols [0,384)
    const __nv_bfloat16* Kp = rowbase + DD;            // cols [384,768)
    const __nv_bfloat16* Vp = rowbase + 2 * DD;        // cols [768,1152)

    const int r  = lane >> 2;
    const int cq = lane & 3;
    const int wq = wid * 16;
    const int lr = lane & 15, lc = lane >> 4;
    const int g8 = lane >> 3, l7 = lane & 7;

    auto issueKV = [&](int k0, int stg) {
        __nv_bfloat16* Kst = fsm + FL_Q_ELEMS + (size_t)stg * 2 * FL_KV_ELEMS;
        __nv_bfloat16* Vst = Kst + FL_KV_ELEMS;
        #pragma unroll
        for (int it = 0; it < 2; it++) {
            int c   = tid + it * 256;
            int row = c >> 3;
            int c8  = (c & 7) * 8;
            cpa16(sptr(&Kst[row * FSTR + c8]), Kp + (size_t)(k0 + row) * RSQ + c8);
            cpa16(sptr(&Vst[row * FSTR + c8]), Vp + (size_t)(k0 + row) * RSQ + c8);
        }
    };

    issueKV(0, 0); cp_commit();
    issueKV(FKT, 1); cp_commit();

    #pragma unroll
    for (int it = 0; it < 4; it++) {
        int id  = tid + it * 256;
        int row = id >> 3;
        int c8  = (id & 7) << 3;
        *(uint4*)&Qs[row * FSTR + c8] =
            *(const uint4*)(Qp + (size_t)(q0 + row) * RSQ + c8);
    }
    __syncthreads();

    unsigned qa[4][4];
    #pragma unroll
    for (int kat = 0; kat < 4; kat++)
        ldsm_x4(qa[kat][0], qa[kat][1], qa[kat][2], qa[kat][3],
                sptr(&Qs[(wq + lr) * FSTR + kat * 16 + lc * 8]));

    float O[8][4];
    float lrow[2];
    lrow[0] = 0.0f; lrow[1] = 0.0f;
    #pragma unroll
    for (int j = 0; j < 8; j++)
        #pragma unroll
        for (int t = 0; t < 4; t++) O[j][t] = 0.0f;

    const int NKT = NN / FKT;
    for (int kt = 0; kt < NKT; kt++) {
        cp_wait<1>();
        __syncthreads();
        const int stg = kt % FSTAGES;
        if (kt + 2 < NKT) {
            int ns = stg + 2; if (ns >= FSTAGES) ns -= FSTAGES;
            issueKV((kt + 2) * FKT, ns); cp_commit();
        }

        __nv_bfloat16* Ks = fsm + FL_Q_ELEMS + (size_t)stg * 2 * FL_KV_ELEMS;
        __nv_bfloat16* Vs = Ks + FL_KV_ELEMS;

        #pragma unroll
        for (int kc = 0; kc < 4; kc++) {
            float s0[4] = {0.0f, 0.0f, 0.0f, 0.0f};
            float s1[4] = {0.0f, 0.0f, 0.0f, 0.0f};
            #pragma unroll
            for (int kat = 0; kat < 4; kat++) {
                unsigned b0, b1, b2, b3;
                ldsm_x4(b0, b1, b2, b3,
                    sptr(&Ks[(kc * 16 + (g8 >> 1) * 8 + l7) * FSTR
                             + kat * 16 + (g8 & 1) * 8]));
                mma_bf16(s0, qa[kat][0], qa[kat][1], qa[kat][2], qa[kat][3], b0, b1);
                mma_bf16(s1, qa[kat][0], qa[kat][1], qa[kat][2], qa[kat][3], b2, b3);
            }

            unsigned pa[4];
            {
                float p0 = ex2f(s0[0]);
                float p1 = ex2f(s0[1]);
                float p2 = ex2f(s0[2]);
                float p3 = ex2f(s0[3]);
                lrow[0] += p0 + p1;
                lrow[1] += p2 + p3;
                pa[0] = pack_bf16(p0, p1);
                pa[1] = pack_bf16(p2, p3);
                float q0f = ex2f(s1[0]);
                float q1f = ex2f(s1[1]);
                float q2f = ex2f(s1[2]);
                float q3f = ex2f(s1[3]);
                lrow[0] += q0f + q1f;
                lrow[1] += q2f + q3f;
                pa[2] = pack_bf16(q0f, q1f);
                pa[3] = pack_bf16(q2f, q3f);
            }

            #pragma unroll
            for (int nd = 0; nd < 4; nd++) {
                unsigned b0, b1, b2, b3;
                ldsm_x4_t(b0, b1, b2, b3,
                    sptr(&Vs[(kc * 16 + (g8 & 1) * 8 + l7) * FSTR
                             + nd * 16 + (g8 >> 1) * 8]));
                mma_bf16(O[2 * nd],     pa[0], pa[1], pa[2], pa[3], b0, b1);
                mma_bf16(O[2 * nd + 1], pa[0], pa[1], pa[2], pa[3], b2, b3);
            }
        }
    }

    #pragma unroll
    for (int half = 0; half < 2; half++) {
        float lf = lrow[half];
        lf += __shfl_xor_sync(0xffffffffu, lf, 1);
        lf += __shfl_xor_sync(0xffffffffu, lf, 2);
        float inv = 1.0f / lf;
        const int gq = q0 + wq + r + 8 * half;
        const int f0 = 2 * half, f1 = f0 + 1;
        #pragma unroll
        for (int na = 0; na < 8; na++) {
            *(unsigned*)(out + ((size_t)(b * NN + gq)) * DD
                               + h * DH + na * 8 + 2 * cq) =
                pack_bf16(O[na][f0] * inv, O[na][f1] * inv);
        }
    }
}

// ---------------------------------------------------------------------------
// kNN top-8 (matches jax: value = (sq_q + sq_m) - 2*dot, smallest-8, stable)
// ---------------------------------------------------------------------------
__global__ void __launch_bounds__(256) knn_kernel(
    const float* __restrict__ coords, int* __restrict__ out)
{
    __shared__ float xs[NN], ys[NN], zs[NN];
    const int b = blockIdx.y;
    const int q = blockIdx.x * 256 + threadIdx.x;
    const float* cb = coords + (size_t)b * NN * 3;

    for (int i = threadIdx.x; i < NN; i += 256) {
        xs[i] = cb[i * 3 + 0];
        ys[i] = cb[i * 3 + 1];
        zs[i] = cb[i * 3 + 2];
    }
    __syncthreads();

    const float qx = xs[q], qy = ys[q], qz = zs[q];
    const float sqq = qx * qx + qy * qy + qz * qz;

    float bd[KNN_K];
    int   bi[KNN_K];
    #pragma unroll
    for (int i = 0; i < KNN_K; i++) { bd[i] = 3.4e38f; bi[i] = 0; }
    float worst = 3.4e38f;

    for (int mI = 0; mI < NN; mI++) {
        float x = xs[mI], y = ys[mI], z = zs[mI];
        float sqm = x * x + y * y + z * z;
        float dot = qx * x + qy * y + qz * z;
        float v = (sqq + sqm) - 2.0f * dot;
        if (v < worst) {
            int j = KNN_K - 1;
            while (j > 0 && bd[j - 1] > v) {
                bd[j] = bd[j - 1];
                bi[j] = bi[j - 1];
                j--;
            }
            bd[j] = v;
            bi[j] = mI;
            worst = bd[KNN_K - 1];
        }
    }

    int* orow = out + ((size_t)(b * NN + q)) * KNN_K;
    #pragma unroll
    for (int i = 0; i < KNN_K; i++) orow[i] = bi[i];
}

// ---------------------------------------------------------------------------
// Graph neighbor attention: one block per (b,n), 128 threads, bf16 out
// ---------------------------------------------------------------------------
__global__ void __launch_bounds__(128) graphattn_kernel(
    const float* __restrict__ gq, const float* __restrict__ gk,
    const float* __restrict__ gv, const int* __restrict__ knn,
    __nv_bfloat16* __restrict__ out)
{
    const int blk  = blockIdx.x;
    const int b    = blk >> 12;
    const int tid  = threadIdx.x;
    const int wid  = tid >> 5;
    const int lane = tid & 31;

    __shared__ float ssc[KNN_K];
    __shared__ int   sidx[KNN_K];
    if (tid < KNN_K) sidx[tid] = knn[(size_t)blk * KNN_K + tid];
    __syncthreads();

    const float* qr = gq + (size_t)blk * DD;

    #pragma unroll
    for (int t = 0; t < 2; t++) {
        int kk = wid + t * 4;
        const float* kr = gk + ((size_t)(b * NN + sidx[kk])) * DD;
        float dot = 0.0f;
        for (int c = lane; c < DD; c += 32) dot = fmaf(qr[c], kr[c], dot);
        #pragma unroll
        for (int off = 16; off; off >>= 1)
            dot += __shfl_xor_sync(0xffffffffu, dot, off);
        if (lane == 0) ssc[kk] = dot;
    }
    __syncthreads();

    float sc[KNN_K];
    float mx = -3.0e38f;
    #pragma unroll
    for (int kk = 0; kk < KNN_K; kk++) {
        sc[kk] = ssc[kk] * 0.05103103630798288f;
        mx = fmaxf(mx, sc[kk]);
    }
    float sum = 0.0f;
    #pragma unroll
    for (int kk = 0; kk < KNN_K; kk++) { sc[kk] = __expf(sc[kk] - mx); sum += sc[kk]; }
    float inv = 1.0f / sum;

    float o0 = 0.0f, o1 = 0.0f, o2 = 0.0f;
    #pragma unroll
    for (int kk = 0; kk < KNN_K; kk++) {
        const float* vr = gv + ((size_t)(b * NN + sidx[kk])) * DD;
        float a = sc[kk] * inv;
        o0 = fmaf(a, vr[tid],       o0);
        o1 = fmaf(a, vr[tid + 128], o1);
        o2 = fmaf(a, vr[tid + 256], o2);
    }
    __nv_bfloat16* orow = out + (size_t)blk * DD;
    orow[tid]       = __float2bfloat16(o0);
    orow[tid + 128] = __float2bfloat16(o1);
    orow[tid + 256] = __float2bfloat16(o2);
}

// ---------------------------------------------------------------------------
// Host launcher — fork/join streams (R10 structure, best known: 481.6 us):
//   sKnn: kNN (coords only)
//   sGeo: LN1 -> gq/gk/gv GEMM -> graph-attn
//   sPre: fused attn-out x merge weight + combined bias precompute
//   main: wcvt -> QKV GEMM -> flash -> merge -> LN2 -> FFN1 -> FFN2
// ---------------------------------------------------------------------------
extern "C" void kernel_launch(void* const* d_in, const int* in_sizes, int n_in,
                              void* d_out, int out_size)
{
    const float* coords     = (const float*)d_in[0];
    const float* features   = (const float*)d_in[1];
    const float* ln1_g      = (const float*)d_in[2];
    const float* ln1_b      = (const float*)d_in[3];
    const float* w_qkv      = (const float*)d_in[4];
    const float* w_attn_out = (const float*)d_in[5];
    const float* b_attn_out = (const float*)d_in[6];
    const float* w_gq       = (const float*)d_in[7];
    const float* w_gk       = (const float*)d_in[8];
    const float* w_gv       = (const float*)d_in[9];
    const float* w_merge    = (const float*)d_in[10];
    const float* b_merge    = (const float*)d_in[11];
    const float* ln2_g      = (const float*)d_in[12];
    const float* ln2_b      = (const float*)d_in[13];
    const float* w_ff1      = (const float*)d_in[14];
    const float* b_ff1      = (const float*)d_in[15];
    const float* w_ff2      = (const float*)d_in[16];
    const float* b_ff2      = (const float*)d_in[17];
    float* outp = (float*)d_out;

    __nv_bfloat16 *NF, *QKVb, *ATTN, *GEOM, *H2, *G1, *WB, *WM2;
    float *GQ, *GK, *GV, *F2, *BC, *ZB;
    int* KNNp;
    cudaGetSymbolAddress((void**)&NF,    g_NF);
    cudaGetSymbolAddress((void**)&QKVb,  g_QKV);
    cudaGetSymbolAddress((void**)&GQ,    g_GQ);
    cudaGetSymbolAddress((void**)&GK,    g_GK);
    cudaGetSymbolAddress((void**)&GV,    g_GV);
    cudaGetSymbolAddress((void**)&ATTN,  g_ATTN);
    cudaGetSymbolAddress((void**)&GEOM,  g_GEOM);
    cudaGetSymbolAddress((void**)&F2,    g_F2);
    cudaGetSymbolAddress((void**)&H2,    g_H2);
    cudaGetSymbolAddress((void**)&G1,    g_G1);
    cudaGetSymbolAddress((void**)&WB,    g_WB);
    cudaGetSymbolAddress((void**)&WM2,   g_WM2);
    cudaGetSymbolAddress((void**)&BC,    g_BC);
    cudaGetSymbolAddress((void**)&ZB,    g_ZB);
    cudaGetSymbolAddress((void**)&KNNp,  g_KNN);

    cudaFuncSetAttribute(gemm_bf<7, false>,
        cudaFuncAttributeMaxDynamicSharedMemorySize, SMEM_GEMM);
    cudaFuncSetAttribute(gemm_bf<5, false>,
        cudaFuncAttributeMaxDynamicSharedMemorySize, SMEM_GEMM);
    cudaFuncSetAttribute(gemm_bf<1, false>,
        cudaFuncAttributeMaxDynamicSharedMemorySize, SMEM_GEMM);
    cudaFuncSetAttribute(gemm_bf<2, false>,
        cudaFuncAttributeMaxDynamicSharedMemorySize, SMEM_GEMM);
    cudaFuncSetAttribute(gemm_bf<3, false>,
        cudaFuncAttributeMaxDynamicSharedMemorySize, SMEM_GEMM);
    cudaFuncSetAttribute(gemm_bf<3, true>,
        cudaFuncAttributeMaxDynamicSharedMemorySize, SMEM_GEMM);
    cudaFuncSetAttribute(flash_tc,
        cudaFuncAttributeMaxDynamicSharedMemorySize, FL_BYTES);

    cudaStream_t sGeo, sKnn, sPre;
    cudaStreamCreateWithFlags(&sGeo, cudaStreamNonBlocking);
    cudaStreamCreateWithFlags(&sKnn, cudaStreamNonBlocking);
    cudaStreamCreateWithFlags(&sPre, cudaStreamNonBlocking);
    cudaEvent_t evRoot, evW, evLn1, evKnn, evGeom, evPre;
    cudaEventCreateWithFlags(&evRoot, cudaEventDisableTiming);
    cudaEventCreateWithFlags(&evW,    cudaEventDisableTiming);
    cudaEventCreateWithFlags(&evLn1,  cudaEventDisableTiming);
    cudaEventCreateWithFlags(&evKnn,  cudaEventDisableTiming);
    cudaEventCreateWithFlags(&evGeom, cudaEventDisableTiming);
    cudaEventCreateWithFlags(&evPre,  cudaEventDisableTiming);

    // ---- root fork ----
    cudaEventRecord(evRoot, 0);
    cudaStreamWaitEvent(sKnn, evRoot, 0);
    knn_kernel<<<dim3(NN / 256, BB), 256, 0, sKnn>>>(coords, KNNp);
    cudaEventRecord(evKnn, sKnn);

    cudaStreamWaitEvent(sGeo, evRoot, 0);
    ln_kernel<<<ROWS, 128, 0, sGeo>>>(features, ln1_g, ln1_b, NF);
    cudaEventRecord(evLn1, sGeo);

    // ---- main: pack weights ----
    wcvt_kernel<<<(TOTW / 4 + 255) / 256, 256>>>(
        w_qkv, w_gq, w_gk, w_gv, w_attn_out, w_merge, w_ff1, w_ff2, WB);
    cudaEventRecord(evW, 0);

    // ---- precompute stream: fused merge weight + bias ----
    cudaStreamWaitEvent(sPre, evW, 0);
    gemm_bf<1, false><<<dim3(3, 3), 256, SMEM_GEMM, sPre>>>(
        WB + OFF_ATT, nullptr, WB + OFF_MRG, ZB, nullptr,
        WM2, nullptr, nullptr, DD, DD, DD);
    wcopy_kernel<<<(DD * DD / 8 + 255) / 256, 256, 0, sPre>>>(
        WB + OFF_MRG + DD * DD, WM2 + DD * DD);
    biascomb_kernel<<<1, DD, 0, sPre>>>(b_attn_out, w_merge, b_merge, BC);
    cudaEventRecord(evPre, sPre);

    // ---- geometry branch (sGeo, after LN1 on same stream) ----
    cudaStreamWaitEvent(sGeo, evW, 0);
    gemm_bf<5, false><<<dim3(1152 / 128, ROWS / 128), 256, SMEM_GEMM, sGeo>>>(
        NF, nullptr, WB + OFF_GQ, nullptr, nullptr,
        GQ, GK, GV, ROWS, DD, DD);
    cudaStreamWaitEvent(sGeo, evKnn, 0);
    graphattn_kernel<<<ROWS, 128, 0, sGeo>>>(GQ, GK, GV, KNNp, GEOM);
    cudaEventRecord(evGeom, sGeo);

    // ---- attention branch (main stream) ----
    cudaStreamWaitEvent(0, evLn1, 0);
    gemm_bf<7, false><<<dim3(RSQ / 128, ROWS / 128), 256, SMEM_GEMM>>>(
        NF, nullptr, WB + OFF_QKV, nullptr, nullptr,
        QKVb, nullptr, nullptr, ROWS, RSQ, DD);
    flash_tc<<<dim3(NN / FQ, BB * HH), 256, FL_BYTES>>>(QKVb, ATTN);

    // ---- join + fused merge + serial tail ----
    cudaStreamWaitEvent(0, evGeom, 0);
    cudaStreamWaitEvent(0, evPre, 0);
    gemm_bf<3, true><<<dim3(DD / 128, ROWS / 128), 256, SMEM_GEMM>>>(
        ATTN, GEOM, WM2, BC, features,
        F2, nullptr, nullptr, ROWS, DD, 2 * DD);
    ln_kernel<<<ROWS, 128>>>(F2, ln2_g, ln2_b, H2);
    gemm_bf<2, false><<<dim3(2 * DD / 128, ROWS / 128), 256, SMEM_GEMM>>>(
        H2, nullptr, WB + OFF_FF1, b_ff1, nullptr,
        G1, nullptr, nullptr, ROWS, 2 * DD, DD);
    gemm_bf<3, false><<<dim3(DD / 128, ROWS / 128), 256, SMEM_GEMM>>>(
        G1, nullptr, WB + OFF_FF2, b_ff2, F2,
        outp, nullptr, nullptr, ROWS, DD, 2 * DD);

    cudaEventDestroy(evRoot);
    cudaEventDestroy(evW);
    cudaEventDestroy(evLn1);
    cudaEventDestroy(evKnn);
    cudaEventDestroy(evGeom);
    cudaEventDestroy(evPre);
    cudaStreamDestroy(sGeo);
    cudaStreamDestroy(sKnn);
    cudaStreamDestroy(sPre);
}